// round 2
// baseline (speedup 1.0000x reference)
#include <cuda_runtime.h>

// QNADE_3521873182819 — autoregressive NADE wavefunction evaluation.
// Key restructuring: pre-activation is a running rank-1 accumulation over sites,
// kept in registers per thread. Per step: tanh(acc) -> 2-column dot vs W2 ->
// reduce -> tanh/normalize/select -> multiply into running product.
//
// N=8192 samples, D=64 sites, H=4096 hidden, M=2.

#define N_SAMP   8192
#define D_SITES  64
#define H_DIM    4096
#define B_SAMP   4          // samples per CTA
#define THREADS  512
#define HPART    128        // threads per sample
#define PER_THR  32         // H_DIM / HPART register accumulators per thread

// tanh(x) = (e^{2x}-1)/(e^{2x}+1) via ex2.approx + rcp.approx.
// abs error ~1e-7, rel error ~1e-6 for |x| <~ 3 (our pre-activations are a
// random walk with std ~0.4, max ~2.5). Far more accurate than tanh.approx.
__device__ __forceinline__ float fast_tanh(float x) {
    float e;
    // 2 * log2(e) = 2.885390081777927
    asm("ex2.approx.f32 %0, %1;" : "=f"(e) : "f"(x * 2.8853900817779268f));
    float r;
    asm("rcp.approx.f32 %0, %1;" : "=f"(r) : "f"(e + 1.0f));
    return (e - 1.0f) * r;
}

__global__ __launch_bounds__(THREADS, 2)
void qnade_kernel(const float* __restrict__ x,
                  const float* __restrict__ W1,
                  const float* __restrict__ b1,
                  const float* __restrict__ W2,
                  const float* __restrict__ b2,
                  float* __restrict__ out)
{
    // dynamic smem layout (floats):
    //   W1s : H_DIM                     (16 KB) — current W1 row
    //   W2s : H_DIM float2 = 2*H_DIM    (32 KB) — (w2[h,0], w2[h,1]) pairs
    //   Xs  : B_SAMP * D_SITES          (1 KB)  — this CTA's spin block
    //   red : 16 float2                         — per-warp dot partials
    extern __shared__ float smem[];
    float*  W1s = smem;
    float2* W2s = (float2*)(smem + H_DIM);
    float*  Xs  = smem + 3 * H_DIM;
    float2* red = (float2*)(Xs + B_SAMP * D_SITES);

    const int t    = threadIdx.x;
    const int nl   = t >> 7;      // local sample 0..3
    const int hp   = t & 127;     // h partition 0..127
    const int n0   = blockIdx.x * B_SAMP;
    const int warp = t >> 5;
    const int lane = t & 31;
    const bool leader = (hp == 0);

    // Stage W2 (float2-contiguous in gmem: W2 is [H,2] row-major).
    const float2* W2g = (const float2*)W2;
    #pragma unroll
    for (int i = 0; i < H_DIM / THREADS; i++)
        W2s[t + i * THREADS] = W2g[t + i * THREADS];

    // Stage this CTA's x block.
    for (int i = t; i < B_SAMP * D_SITES; i += THREADS)
        Xs[i] = x[(size_t)(n0 + i / D_SITES) * D_SITES + (i % D_SITES)];

    // Register accumulator: pre-activation, initialized to b1 (d=0: empty mask).
    float acc[PER_THR];
    #pragma unroll
    for (int i = 0; i < PER_THR; i++)
        acc[i] = b1[hp + (i << 7)];

    const float b20 = b2[0], b21 = b2[1];
    float wav = 1.0f;

    for (int d = 0; d < D_SITES; d++) {
        __syncthreads();   // prev step's red consumed; W1s free

        // Stage W1 row d (4096 floats, float4-vectorized, 2 per thread).
        {
            const float4* w1row = (const float4*)(W1 + (size_t)d * H_DIM);
            float4* w1s4 = (float4*)W1s;
            #pragma unroll
            for (int i = 0; i < H_DIM / 4 / THREADS; i++)
                w1s4[t + i * THREADS] = w1row[t + i * THREADS];
        }
        __syncthreads();   // W1s ready

        const float xs = Xs[nl * D_SITES + d];
        float d0 = 0.0f, d1 = 0.0f;
        #pragma unroll
        for (int i = 0; i < PER_THR; i++) {
            const int h = hp + (i << 7);
            const float tv = fast_tanh(acc[i]);
            const float2 w2 = W2s[h];
            d0 = fmaf(tv, w2.x, d0);
            d1 = fmaf(tv, w2.y, d1);
            acc[i] = fmaf(xs, W1s[h], acc[i]);   // add site d AFTER using acc
        }

        // Reduce d0,d1 over the 128 threads (4 warps) of this sample.
        #pragma unroll
        for (int o = 16; o; o >>= 1) {
            d0 += __shfl_xor_sync(0xffffffffu, d0, o);
            d1 += __shfl_xor_sync(0xffffffffu, d1, o);
        }
        if (lane == 0) red[warp] = make_float2(d0, d1);
        __syncthreads();   // red ready

        if (leader) {
            const float2 r0 = red[nl * 4 + 0];
            const float2 r1 = red[nl * 4 + 1];
            const float2 r2 = red[nl * 4 + 2];
            const float2 r3 = red[nl * 4 + 3];
            const float z0 = ((r0.x + r1.x) + (r2.x + r3.x)) + b20;
            const float z1 = ((r0.y + r1.y) + (r2.y + r3.y)) + b21;
            const float t0 = tanhf(z0);           // accurate: only 64 calls/sample
            const float t1 = tanhf(z1);
            float nrm = sqrtf(t0 * t0 + t1 * t1);
            nrm = fmaxf(nrm, 1e-12f);
            const float sel = (xs > 0.0f ? t0 : t1) / nrm;
            wav *= sel;
        }
    }

    if (leader) out[n0 + nl] = wav;
}

extern "C" void kernel_launch(void* const* d_in, const int* in_sizes, int n_in,
                              void* d_out, int out_size) {
    const float* x  = (const float*)d_in[0];   // [8192, 64]
    const float* W1 = (const float*)d_in[1];   // [64, 4096]
    const float* b1 = (const float*)d_in[2];   // [4096]
    const float* W2 = (const float*)d_in[3];   // [4096, 2]
    const float* b2 = (const float*)d_in[4];   // [2]
    float* out = (float*)d_out;                // [8192]

    const int smem_bytes =
        (3 * H_DIM + B_SAMP * D_SITES) * (int)sizeof(float) + 16 * (int)sizeof(float2);

    cudaFuncSetAttribute(qnade_kernel,
                         cudaFuncAttributeMaxDynamicSharedMemorySize, smem_bytes);

    qnade_kernel<<<N_SAMP / B_SAMP, THREADS, smem_bytes>>>(x, W1, b1, W2, b2, out);
}

// round 6
// speedup vs baseline: 1.1661x; 1.1661x over previous
#include <cuda_runtime.h>
#include <cstdint>

// QNADE — autoregressive NADE wavefunction evaluation. N=8192, D=64, H=4096, M=2.
// Running rank-1 pre-activation accumulator in registers; per step:
// tanh (paired, shared rcp) -> packed f32x2 dots vs W2 -> reduce -> select -> product.

#define N_SAMP   8192
#define D_SITES  64
#define H_DIM    4096
#define B_SAMP   4
#define THREADS  512
#define HPART    128          // threads per sample
#define PER_THR  32           // h-elements per thread (contiguous chunk)
#define NPAIR    16
#define PAD_CH   36           // words per 32-float chunk (4-word pad -> conflict-free LDS.128)
#define W1_FLOATS (HPART * PAD_CH)   // 4608 floats per W1 buffer

typedef unsigned long long ull;

__device__ __forceinline__ ull pk(float a, float b) {
    ull r; asm("mov.b64 %0, {%1, %2};" : "=l"(r) : "f"(a), "f"(b)); return r;
}
__device__ __forceinline__ void upk(ull v, float& a, float& b) {
    asm("mov.b64 {%0, %1}, %2;" : "=f"(a), "=f"(b) : "l"(v));
}
__device__ __forceinline__ ull fma2(ull a, ull b, ull c) {
    ull d; asm("fma.rn.f32x2 %0, %1, %2, %3;" : "=l"(d) : "l"(a), "l"(b), "l"(c)); return d;
}
__device__ __forceinline__ ull mul2(ull a, ull b) {
    ull d; asm("mul.rn.f32x2 %0, %1, %2;" : "=l"(d) : "l"(a), "l"(b)); return d;
}
__device__ __forceinline__ void cp16(uint32_t dst, const void* src) {
    asm volatile("cp.async.ca.shared.global [%0], [%1], 16;" :: "r"(dst), "l"(src));
}

// Two tanh evaluations sharing one rcp, packed dot/acc updates.
// tanh(x) = 1 - 2/(exp2(2*log2e*x) + 1);  1/u0 = rcp(u0*u1)*u1.
__device__ __forceinline__ ull pair_step(ull acc, ull w1, ull wx, ull wy,
                                         ull xs2, ull c2, ull& d0v, ull& d1v) {
    ull s = mul2(acc, c2);
    float s0, s1; upk(s, s0, s1);
    float e0, e1;
    asm("ex2.approx.f32 %0, %1;" : "=f"(e0) : "f"(s0));
    asm("ex2.approx.f32 %0, %1;" : "=f"(e1) : "f"(s1));
    const float u0 = e0 + 1.0f, u1 = e1 + 1.0f;
    float r;
    asm("rcp.approx.f32 %0, %1;" : "=f"(r) : "f"(u0 * u1));
    const float q0 = r * u1, q1 = r * u0;
    const float t0 = fmaf(-2.0f, q0, 1.0f);      // FFMA-imm, rt=1
    const float t1 = fmaf(-2.0f, q1, 1.0f);
    const ull tv = pk(t0, t1);
    d0v = fma2(tv, wx, d0v);
    d1v = fma2(tv, wy, d1v);
    return fma2(xs2, w1, acc);
}

__global__ __launch_bounds__(THREADS, 2)
void qnade_kernel(const float* __restrict__ x,
                  const float* __restrict__ W1,
                  const float* __restrict__ b1,
                  const float* __restrict__ W2,
                  const float* __restrict__ b2,
                  float* __restrict__ out)
{
    // smem (floats): W1s[2][4608] | W2xs[4608] | W2ys[4608] | Xs[256] | red[2][16] float2
    extern __shared__ float smem[];
    float*  W1s  = smem;
    float*  W2xs = smem + 2 * W1_FLOATS;
    float*  W2ys = W2xs + W1_FLOATS;
    float*  Xs   = W2ys + W1_FLOATS;
    float2* red  = (float2*)(Xs + B_SAMP * D_SITES);

    const int t    = threadIdx.x;
    const int nl   = t >> 7;
    const int hp   = t & 127;
    const int n0   = blockIdx.x * B_SAMP;
    const int warp = t >> 5;
    const int lane = t & 31;
    const bool leader = (hp == 0);
    const uint32_t smem_u32 = (uint32_t)__cvta_generic_to_shared(smem);

    // Stage W2 split into x/y arrays, chunk-padded layout.
    const float2* W2g = (const float2*)W2;
    #pragma unroll
    for (int i = t; i < H_DIM; i += THREADS) {
        const float2 g = W2g[i];
        const int c = i >> 5, k = i & 31;
        W2xs[c * PAD_CH + k] = g.x;
        W2ys[c * PAD_CH + k] = g.y;
    }
    // Stage spins.
    for (int i = t; i < B_SAMP * D_SITES; i += THREADS)
        Xs[i] = x[(size_t)(n0 + i / D_SITES) * D_SITES + (i % D_SITES)];

    // Stage W1 row 0 into buffer 0 via cp.async (padded layout, 16B granules).
    #pragma unroll
    for (int j = t; j < H_DIM / 4; j += THREADS) {
        const int c = j >> 3, w = (j & 7) << 2;
        cp16(smem_u32 + (uint32_t)(c * PAD_CH + w) * 4u, W1 + 4 * j);
    }
    asm volatile("cp.async.commit_group;");

    // Register accumulator = b1 (step 0: empty mask), packed pairs.
    ull acc2[NPAIR];
    {
        const ulonglong2* b1v = (const ulonglong2*)(b1 + hp * PER_THR);
        #pragma unroll
        for (int q = 0; q < 8; q++) {
            const ulonglong2 v = b1v[q];
            acc2[2 * q] = v.x; acc2[2 * q + 1] = v.y;
        }
    }

    const float b20 = b2[0], b21 = b2[1];
    const ull C2 = pk(2.8853900817779268f, 2.8853900817779268f);  // 2*log2(e)
    float wav = 1.0f;
    int buf = 0;

    asm volatile("cp.async.wait_group 0;" ::: "memory");
    __syncthreads();

    const float* WXb = W2xs + hp * PAD_CH;
    const float* WYb = W2ys + hp * PAD_CH;

    for (int d = 0; d < D_SITES; d++) {
        // Prefetch W1 row d+1 into the other buffer (safe: last read of it was
        // before the barrier that ended step d-1).
        if (d + 1 < D_SITES) {
            const float* src = W1 + (size_t)(d + 1) * H_DIM;
            const uint32_t dbase = smem_u32 + (uint32_t)((buf ^ 1) * W1_FLOATS) * 4u;
            #pragma unroll
            for (int j = t; j < H_DIM / 4; j += THREADS) {
                const int c = j >> 3, w = (j & 7) << 2;
                cp16(dbase + (uint32_t)(c * PAD_CH + w) * 4u, src + 4 * j);
            }
        }
        asm volatile("cp.async.commit_group;");

        const float xs = Xs[nl * D_SITES + d];
        const ull xs2 = pk(xs, xs);
        const float* W1b = W1s + buf * W1_FLOATS + hp * PAD_CH;

        ull d0v = 0ull, d1v = 0ull;   // (0.f, 0.f)
        #pragma unroll
        for (int q = 0; q < 8; q++) {
            const ulonglong2 w1q = *(const ulonglong2*)(W1b + 4 * q);
            const ulonglong2 wxq = *(const ulonglong2*)(WXb + 4 * q);
            const ulonglong2 wyq = *(const ulonglong2*)(WYb + 4 * q);
            acc2[2 * q]     = pair_step(acc2[2 * q],     w1q.x, wxq.x, wyq.x, xs2, C2, d0v, d1v);
            acc2[2 * q + 1] = pair_step(acc2[2 * q + 1], w1q.y, wxq.y, wyq.y, xs2, C2, d0v, d1v);
        }
        float a, b;
        upk(d0v, a, b); float d0 = a + b;
        upk(d1v, a, b); float d1 = a + b;

        #pragma unroll
        for (int o = 16; o; o >>= 1) {
            d0 += __shfl_xor_sync(0xffffffffu, d0, o);
            d1 += __shfl_xor_sync(0xffffffffu, d1, o);
        }
        float2* redb = red + (d & 1) * 16;
        if (lane == 0) redb[warp] = make_float2(d0, d1);

        asm volatile("cp.async.wait_group 0;" ::: "memory");
        __syncthreads();   // publishes red AND next W1 buffer

        if (leader) {
            const float2 r0 = redb[nl * 4 + 0];
            const float2 r1 = redb[nl * 4 + 1];
            const float2 r2 = redb[nl * 4 + 2];
            const float2 r3 = redb[nl * 4 + 3];
            const float z0 = ((r0.x + r1.x) + (r2.x + r3.x)) + b20;
            const float z1 = ((r0.y + r1.y) + (r2.y + r3.y)) + b21;
            const float t0 = tanhf(z0);
            const float t1 = tanhf(z1);
            float nrm = sqrtf(t0 * t0 + t1 * t1);
            nrm = fmaxf(nrm, 1e-12f);
            wav *= (xs > 0.0f ? t0 : t1) / nrm;
        }
        buf ^= 1;
    }

    if (leader) out[n0 + nl] = wav;
}

extern "C" void kernel_launch(void* const* d_in, const int* in_sizes, int n_in,
                              void* d_out, int out_size) {
    const float* x  = (const float*)d_in[0];
    const float* W1 = (const float*)d_in[1];
    const float* b1 = (const float*)d_in[2];
    const float* W2 = (const float*)d_in[3];
    const float* b2 = (const float*)d_in[4];
    float* out = (float*)d_out;

    const int smem_bytes =
        (4 * W1_FLOATS + B_SAMP * D_SITES) * (int)sizeof(float) + 32 * (int)sizeof(float2);

    cudaFuncSetAttribute(qnade_kernel,
                         cudaFuncAttributeMaxDynamicSharedMemorySize, smem_bytes);

    qnade_kernel<<<N_SAMP / B_SAMP, THREADS, smem_bytes>>>(x, W1, b1, W2, b2, out);
}